// round 1
// baseline (speedup 1.0000x reference)
#include <cuda_runtime.h>
#include <math.h>

// ---------------- problem constants ----------------
#define DIMN   3072
#define HEADS  24
#define HD     128
#define S_HID  3072
#define S_ENC  512
#define SEQ    3584          // S_ENC + S_HID
#define CONDN  1024
#define RANKN  64
#define BLOCKL 2048          // S_HID - CONDN
static const float ATTN_SCALE = 0.08838834764831843f; // 1/sqrt(128)

// ---------------- device scratch (no allocs allowed) ----------------
__device__ float g_Pq[(size_t)S_HID * DIMN];
__device__ float g_Pk[(size_t)S_HID * DIMN];
__device__ float g_Pv[(size_t)S_HID * DIMN];
__device__ float g_Eq[(size_t)S_ENC * DIMN];
__device__ float g_Ek[(size_t)S_ENC * DIMN];
__device__ float g_Ev[(size_t)S_ENC * DIMN];
__device__ float g_Dt[(size_t)CONDN * RANKN];
__device__ float g_Q[(size_t)HEADS * SEQ * HD];
__device__ float g_K[(size_t)HEADS * SEQ * HD];
__device__ float g_V[(size_t)HEADS * SEQ * HD];
__device__ float g_SA[(size_t)HEADS * S_ENC * SEQ];    // encoder-query scores
__device__ float g_SB[(size_t)HEADS * CONDN * CONDN];  // cond-block scores
__device__ float g_AO[(size_t)SEQ * DIMN];             // attention out, [S, DIM]

// ---------------- generic fp32 GEMM ----------------
// TB=true : C = alpha * A[M,K] * B[N,K]^T  (+bias, +beta*C)
// TB=false: C = alpha * A[M,K] * B[K,N]    (+bias, +beta*C)
// 128x128x16 tile, 256 threads, 8x8 per-thread micro-tile (2x2 quadrants of 4x4).
#define BM 128
#define BN 128
#define BK 16

template <bool TB>
__global__ __launch_bounds__(256, 2)
void gemm_k(const float* __restrict__ A, const float* __restrict__ B,
            const float* __restrict__ bias, float* __restrict__ C,
            int M, int N, int K, int lda, int ldb, int ldc,
            long long sA, long long sB, long long sC,
            float alpha, const float* __restrict__ alpha_ptr, float beta)
{
    __shared__ float As[BK][BM + 4];
    __shared__ float Bs[BK][BN + 4];

    const float* Ab = A + (long long)blockIdx.z * sA;
    const float* Bb = B + (long long)blockIdx.z * sB;
    float*       Cb = C + (long long)blockIdx.z * sC;

    const int m0 = blockIdx.y * BM;
    const int n0 = blockIdx.x * BN;
    const int tid = threadIdx.x;
    const int tx = tid & 15;
    const int ty = tid >> 4;

    float acc[2][2][4][4];
#pragma unroll
    for (int a = 0; a < 2; a++)
#pragma unroll
        for (int b = 0; b < 2; b++)
#pragma unroll
            for (int i = 0; i < 4; i++)
#pragma unroll
                for (int j = 0; j < 4; j++) acc[a][b][i][j] = 0.f;

    for (int k0 = 0; k0 < K; k0 += BK) {
        // ---- load A tile (transpose into As[k][m]) ----
        {
            const int mi = tid >> 2;
            const int kq = (tid & 3) << 2;
#pragma unroll
            for (int half = 0; half < 2; half++) {
                const int m = mi + half * 64;
                const int gm = m0 + m;
                float4 v = make_float4(0.f, 0.f, 0.f, 0.f);
                if (gm < M)
                    v = *(const float4*)(Ab + (long long)gm * lda + k0 + kq);
                As[kq + 0][m] = v.x; As[kq + 1][m] = v.y;
                As[kq + 2][m] = v.z; As[kq + 3][m] = v.w;
            }
        }
        // ---- load B tile into Bs[k][n] ----
        if (TB) {
            const int ni = tid >> 2;
            const int kq = (tid & 3) << 2;
#pragma unroll
            for (int half = 0; half < 2; half++) {
                const int n = ni + half * 64;
                const int gn = n0 + n;
                float4 v = make_float4(0.f, 0.f, 0.f, 0.f);
                if (gn < N)
                    v = *(const float4*)(Bb + (long long)gn * ldb + k0 + kq);
                Bs[kq + 0][n] = v.x; Bs[kq + 1][n] = v.y;
                Bs[kq + 2][n] = v.z; Bs[kq + 3][n] = v.w;
            }
        } else {
            const int nq = (tid & 31) << 2;
            const int ki = tid >> 5;
#pragma unroll
            for (int half = 0; half < 2; half++) {
                const int k = ki + half * 8;
                const int gn = n0 + nq;
                float4 v = make_float4(0.f, 0.f, 0.f, 0.f);
                if (gn < N)
                    v = *(const float4*)(Bb + (long long)(k0 + k) * ldb + gn);
                *(float4*)&Bs[k][nq] = v;
            }
        }
        __syncthreads();

#pragma unroll
        for (int kk = 0; kk < BK; kk++) {
            float4 a0 = *(const float4*)&As[kk][ty * 4];
            float4 a1 = *(const float4*)&As[kk][64 + ty * 4];
            float4 b0 = *(const float4*)&Bs[kk][tx * 4];
            float4 b1 = *(const float4*)&Bs[kk][64 + tx * 4];
            float av[2][4] = {{a0.x, a0.y, a0.z, a0.w}, {a1.x, a1.y, a1.z, a1.w}};
            float bv[2][4] = {{b0.x, b0.y, b0.z, b0.w}, {b1.x, b1.y, b1.z, b1.w}};
#pragma unroll
            for (int ih = 0; ih < 2; ih++)
#pragma unroll
                for (int jh = 0; jh < 2; jh++)
#pragma unroll
                    for (int i = 0; i < 4; i++)
#pragma unroll
                        for (int j = 0; j < 4; j++)
                            acc[ih][jh][i][j] += av[ih][i] * bv[jh][j];
        }
        __syncthreads();
    }

    float aE = alpha;
    if (alpha_ptr) aE *= *alpha_ptr;

#pragma unroll
    for (int ih = 0; ih < 2; ih++)
#pragma unroll
        for (int i = 0; i < 4; i++) {
            const int gm = m0 + ih * 64 + ty * 4 + i;
            if (gm >= M) continue;
            float* crow = Cb + (long long)gm * ldc;
#pragma unroll
            for (int jh = 0; jh < 2; jh++) {
                const int gn = n0 + jh * 64 + tx * 4;
                if (gn >= N) continue;
                float4 add = make_float4(0.f, 0.f, 0.f, 0.f);
                if (bias) {
                    add.x = bias[gn]; add.y = bias[gn + 1];
                    add.z = bias[gn + 2]; add.w = bias[gn + 3];
                }
                if (beta != 0.f) {
                    float4 c = *(const float4*)(crow + gn);
                    add.x += beta * c.x; add.y += beta * c.y;
                    add.z += beta * c.z; add.w += beta * c.w;
                }
                float4 o;
                o.x = aE * acc[ih][jh][i][0] + add.x;
                o.y = aE * acc[ih][jh][i][1] + add.y;
                o.z = aE * acc[ih][jh][i][2] + add.z;
                o.w = aE * acc[ih][jh][i][3] + add.w;
                *(float4*)(crow + gn) = o;
            }
        }
}

// ---------------- heads + RMSNorm + RoPE + concat ----------------
__global__ void build_qkv(const float* __restrict__ Pq, const float* __restrict__ Pk,
                          const float* __restrict__ Pv, const float* __restrict__ Eq,
                          const float* __restrict__ Ek, const float* __restrict__ Ev,
                          const float* __restrict__ rc, const float* __restrict__ rs,
                          const float* __restrict__ nqw, const float* __restrict__ nkw,
                          const float* __restrict__ naqw, const float* __restrict__ nakw,
                          float* __restrict__ Q, float* __restrict__ K, float* __restrict__ V)
{
    const int s = blockIdx.x;   // 0..SEQ-1
    const int h = blockIdx.y;   // head
    const int d = threadIdx.x;  // 0..127

    const float *sq, *sk, *sv, *wq, *wk;
    if (s < S_ENC) {
        const long long off = (long long)s * DIMN + h * HD;
        sq = Eq + off; sk = Ek + off; sv = Ev + off;
        wq = naqw; wk = nakw;
    } else {
        const long long off = (long long)(s - S_ENC) * DIMN + h * HD;
        sq = Pq + off; sk = Pk + off; sv = Pv + off;
        wq = nqw; wk = nkw;
    }
    float q = sq[d], k = sk[d], v = sv[d];

    float ssq = q * q, ssk = k * k;
#pragma unroll
    for (int o = 16; o; o >>= 1) {
        ssq += __shfl_xor_sync(0xffffffffu, ssq, o);
        ssk += __shfl_xor_sync(0xffffffffu, ssk, o);
    }
    __shared__ float shq[4], shk[4];
    const int w = d >> 5;
    if ((d & 31) == 0) { shq[w] = ssq; shk[w] = ssk; }
    __syncthreads();
    const float tq = shq[0] + shq[1] + shq[2] + shq[3];
    const float tk = shk[0] + shk[1] + shk[2] + shk[3];

    const float qn = q * rsqrtf(tq * (1.0f / HD) + 1e-6f) * wq[d];
    const float kn = k * rsqrtf(tk * (1.0f / HD) + 1e-6f) * wk[d];

    const float qp = __shfl_xor_sync(0xffffffffu, qn, 1);
    const float kp = __shfl_xor_sync(0xffffffffu, kn, 1);
    const float qr = (d & 1) ? qp : -qp;
    const float kr = (d & 1) ? kp : -kp;

    const float c = rc[(long long)s * HD + d];
    const float sn = rs[(long long)s * HD + d];

    const long long o = ((long long)h * SEQ + s) * HD + d;
    Q[o] = qn * c + qr * sn;
    K[o] = kn * c + kr * sn;
    V[o] = v;
}

// ---------------- row softmax (in place) ----------------
__global__ void softmax_k(float* __restrict__ S, int ncols)
{
    float* r = S + (long long)blockIdx.x * ncols;
    const int tid = threadIdx.x;
    __shared__ float sh[8];

    float m = -INFINITY;
    for (int c = tid; c < ncols; c += 256) m = fmaxf(m, r[c]);
#pragma unroll
    for (int o = 16; o; o >>= 1) m = fmaxf(m, __shfl_xor_sync(0xffffffffu, m, o));
    if ((tid & 31) == 0) sh[tid >> 5] = m;
    __syncthreads();
    float bm = sh[0];
#pragma unroll
    for (int i = 1; i < 8; i++) bm = fmaxf(bm, sh[i]);
    __syncthreads();

    float sum = 0.f;
    for (int c = tid; c < ncols; c += 256) {
        float e = expf(r[c] - bm);
        r[c] = e;
        sum += e;
    }
#pragma unroll
    for (int o = 16; o; o >>= 1) sum += __shfl_xor_sync(0xffffffffu, sum, o);
    if ((tid & 31) == 0) sh[tid >> 5] = sum;
    __syncthreads();
    float bs = 0.f;
#pragma unroll
    for (int i = 0; i < 8; i++) bs += sh[i];
    const float inv = 1.0f / bs;
    for (int c = tid; c < ncols; c += 256) r[c] *= inv;
}

// ---------------- mean(V) per head -> fill rows [1536, 3584) of AO ----------------
// (mask rows >= S_E+COND are fully -1e20; -1e20 absorbs scores in fp32 exactly,
//  so softmax is exactly uniform -> output is mean of V over all keys)
__global__ void meanv_fill(const float* __restrict__ V, float* __restrict__ AO)
{
    const int h = blockIdx.x;
    const int d = threadIdx.x;
    const float* vb = V + (long long)h * SEQ * HD + d;
    float s = 0.f;
    for (int i = 0; i < SEQ; i++) s += vb[(long long)i * HD];
    const float mean = s * (1.0f / SEQ);
    float* o = AO + (long long)(S_ENC + CONDN) * DIMN + h * HD + d;
    for (int r = 0; r < SEQ - S_ENC - CONDN; r++) o[(long long)r * DIMN] = mean;
}

// ---------------- host-side launch helpers ----------------
static void gemm(bool tb, const float* A, const float* B, const float* bias, float* C,
                 int M, int N, int K, int lda, int ldb, int ldc,
                 long long sA, long long sB, long long sC, int batch,
                 float alpha, const float* aptr, float beta)
{
    dim3 g((N + BN - 1) / BN, (M + BM - 1) / BM, batch);
    if (tb)
        gemm_k<true><<<g, 256>>>(A, B, bias, C, M, N, K, lda, ldb, ldc, sA, sB, sC, alpha, aptr, beta);
    else
        gemm_k<false><<<g, 256>>>(A, B, bias, C, M, N, K, lda, ldb, ldc, sA, sB, sC, alpha, aptr, beta);
}

extern "C" void kernel_launch(void* const* d_in, const int* in_sizes, int n_in,
                              void* d_out, int out_size)
{
    const float* hidden = (const float*)d_in[0];
    const float* enc    = (const float*)d_in[1];
    const float* rc     = (const float*)d_in[2];
    const float* rs     = (const float*)d_in[3];
    const float* Wq  = (const float*)d_in[4];
    const float* Wk  = (const float*)d_in[5];
    const float* Wv  = (const float*)d_in[6];
    const float* Wqa = (const float*)d_in[7];
    const float* Wka = (const float*)d_in[8];
    const float* Wva = (const float*)d_in[9];
    const float* Wo  = (const float*)d_in[10];
    const float* Woa = (const float*)d_in[11];
    const float* bq  = (const float*)d_in[12];
    const float* bk  = (const float*)d_in[13];
    const float* bv  = (const float*)d_in[14];
    const float* bqa = (const float*)d_in[15];
    const float* bka = (const float*)d_in[16];
    const float* bva = (const float*)d_in[17];
    const float* bo  = (const float*)d_in[18];
    const float* boa = (const float*)d_in[19];
    const float* nqw  = (const float*)d_in[20];
    const float* nkw  = (const float*)d_in[21];
    const float* naqw = (const float*)d_in[22];
    const float* nakw = (const float*)d_in[23];
    const float* qd = (const float*)d_in[24];
    const float* kd = (const float*)d_in[25];
    const float* vd = (const float*)d_in[26];
    const float* qu = (const float*)d_in[27];
    const float* ku = (const float*)d_in[28];
    const float* vu = (const float*)d_in[29];
    const float* lw = (const float*)d_in[30];

    float *Pq, *Pk, *Pv, *Eq, *Ek, *Ev, *Dt, *Q, *K, *V, *SA, *SB, *AO;
    cudaGetSymbolAddress((void**)&Pq, g_Pq);
    cudaGetSymbolAddress((void**)&Pk, g_Pk);
    cudaGetSymbolAddress((void**)&Pv, g_Pv);
    cudaGetSymbolAddress((void**)&Eq, g_Eq);
    cudaGetSymbolAddress((void**)&Ek, g_Ek);
    cudaGetSymbolAddress((void**)&Ev, g_Ev);
    cudaGetSymbolAddress((void**)&Dt, g_Dt);
    cudaGetSymbolAddress((void**)&Q,  g_Q);
    cudaGetSymbolAddress((void**)&K,  g_K);
    cudaGetSymbolAddress((void**)&V,  g_V);
    cudaGetSymbolAddress((void**)&SA, g_SA);
    cudaGetSymbolAddress((void**)&SB, g_SB);
    cudaGetSymbolAddress((void**)&AO, g_AO);

    float* out = (float*)d_out;

    // 1) base projections (image side): P = hidden @ W^T + b
    gemm(true, hidden, Wq, bq, Pq, S_HID, DIMN, DIMN, DIMN, DIMN, DIMN, 0, 0, 0, 1, 1.f, nullptr, 0.f);
    gemm(true, hidden, Wk, bk, Pk, S_HID, DIMN, DIMN, DIMN, DIMN, DIMN, 0, 0, 0, 1, 1.f, nullptr, 0.f);
    gemm(true, hidden, Wv, bv, Pv, S_HID, DIMN, DIMN, DIMN, DIMN, DIMN, 0, 0, 0, 1, 1.f, nullptr, 0.f);

    // 2) encoder projections
    gemm(true, enc, Wqa, bqa, Eq, S_ENC, DIMN, DIMN, DIMN, DIMN, DIMN, 0, 0, 0, 1, 1.f, nullptr, 0.f);
    gemm(true, enc, Wka, bka, Ek, S_ENC, DIMN, DIMN, DIMN, DIMN, DIMN, 0, 0, 0, 1, 1.f, nullptr, 0.f);
    gemm(true, enc, Wva, bva, Ev, S_ENC, DIMN, DIMN, DIMN, DIMN, DIMN, 0, 0, 0, 1, 1.f, nullptr, 0.f);

    // 3) LoRA (mask keeps only rows [2048,3072) of hidden); sc = lora_w[0] * ALPHA/RANK = lora_w[0]
    const float* downs[3] = {qd, kd, vd};
    const float* ups[3]   = {qu, ku, vu};
    float* Ps[3]          = {Pq, Pk, Pv};
    for (int i = 0; i < 3; i++) {
        gemm(true, hidden + (long long)BLOCKL * DIMN, downs[i], nullptr, Dt,
             CONDN, RANKN, DIMN, DIMN, DIMN, RANKN, 0, 0, 0, 1, 1.f, nullptr, 0.f);
        gemm(true, Dt, ups[i], nullptr, Ps[i] + (long long)BLOCKL * DIMN,
             CONDN, DIMN, RANKN, RANKN, RANKN, DIMN, 0, 0, 0, 1, 1.f, lw, 1.f);
    }

    // 4) heads + RMSNorm + RoPE + concat into [H, S, D]
    build_qkv<<<dim3(SEQ, HEADS), HD>>>(Pq, Pk, Pv, Eq, Ek, Ev, rc, rs,
                                        nqw, nkw, naqw, nakw, Q, K, V);

    // 5) block A: encoder queries (rows 0..511), full keys
    gemm(true, Q, K, nullptr, SA, S_ENC, SEQ, HD, HD, HD, SEQ,
         (long long)SEQ * HD, (long long)SEQ * HD, (long long)S_ENC * SEQ, HEADS,
         ATTN_SCALE, nullptr, 0.f);
    softmax_k<<<HEADS * S_ENC, 256>>>(SA, SEQ);
    gemm(false, SA, V, nullptr, AO, S_ENC, HD, SEQ, SEQ, HD, DIMN,
         (long long)S_ENC * SEQ, (long long)SEQ * HD, HD, HEADS, 1.f, nullptr, 0.f);

    // 6) block B: cond queries (rows 512..1535), keys 512..1535 only
    gemm(true, Q + (long long)S_ENC * HD, K + (long long)S_ENC * HD, nullptr, SB,
         CONDN, CONDN, HD, HD, HD, CONDN,
         (long long)SEQ * HD, (long long)SEQ * HD, (long long)CONDN * CONDN, HEADS,
         ATTN_SCALE, nullptr, 0.f);
    softmax_k<<<HEADS * CONDN, 256>>>(SB, CONDN);
    gemm(false, SB, V + (long long)S_ENC * HD, nullptr, AO + (long long)S_ENC * DIMN,
         CONDN, HD, CONDN, CONDN, HD, DIMN,
         (long long)CONDN * CONDN, (long long)SEQ * HD, HD, HEADS, 1.f, nullptr, 0.f);

    // 7) block C: fully-masked rows -> exactly uniform softmax -> mean of V
    meanv_fill<<<HEADS, HD>>>(V, AO);

    // 8) output projections: hid_out first, then enc_out
    gemm(true, AO + (long long)S_ENC * DIMN, Wo, bo, out,
         S_HID, DIMN, DIMN, DIMN, DIMN, DIMN, 0, 0, 0, 1, 1.f, nullptr, 0.f);
    gemm(true, AO, Woa, boa, out + (long long)S_HID * DIMN,
         S_ENC, DIMN, DIMN, DIMN, DIMN, DIMN, 0, 0, 0, 1, 1.f, nullptr, 0.f);
}

// round 2
// speedup vs baseline: 2.6784x; 2.6784x over previous
#include <cuda_runtime.h>
#include <math.h>
#include <stdint.h>

// ---------------- problem constants ----------------
#define DIMN   3072
#define HEADS  24
#define HD     128
#define S_HID  3072
#define S_ENC  512
#define SEQ    3584          // S_ENC + S_HID
#define CONDN  1024
#define RANKN  64
#define BLOCKL 2048          // S_HID - CONDN
#define NROWS_C (SEQ - S_ENC - CONDN)   // 2048 fully-masked query rows
static const float ATTN_SCALE = 0.08838834764831843f; // 1/sqrt(128)

// ---------------- device scratch (no allocs allowed) ----------------
__device__ float g_Pq[(size_t)S_HID * DIMN];
__device__ float g_Pk[(size_t)S_HID * DIMN];
__device__ float g_Pv[(size_t)S_HID * DIMN];
__device__ float g_Eq[(size_t)S_ENC * DIMN];
__device__ float g_Ek[(size_t)S_ENC * DIMN];
__device__ float g_Ev[(size_t)S_ENC * DIMN];
__device__ float g_Dt[(size_t)CONDN * RANKN];
__device__ float g_Q [(size_t)HEADS * SEQ * HD];
__device__ float g_K [(size_t)HEADS * SEQ * HD];
__device__ float g_Vt[(size_t)HEADS * HD * SEQ];     // V transposed: [h][d][s]
__device__ float g_SA[(size_t)HEADS * S_ENC * SEQ];   // encoder-query scores
__device__ float g_SB[(size_t)HEADS * CONDN * CONDN]; // cond-block scores
__device__ float g_AO[(size_t)(S_ENC + CONDN) * DIMN];// attention out rows 0..1535
__device__ float g_mean[DIMN];                        // mean of V per dim
__device__ float g_vec [DIMN];                        // mean @ Wo^T + bo

// ---------------- tf32 tensor-core GEMM ----------------
// C = alpha * A[M,K] * B[N,K]^T (+bias, +beta*C).  A,B row-major with leading
// dims lda/ldb; batch via blockIdx.z with strides sA/sB/sC.
// 128x128x32 tile, 256 threads (8 warps, warp tile 64x32), cp.async double buffer.
#define BM 128
#define BN 128
#define BK 32
#define ASTR 36   // smem row stride (floats): (g*36+k) mod 32 = 4g+k -> conflict-free frags

__device__ __forceinline__ uint32_t f2tf(float f) {
    uint32_t u;
    asm("cvt.rna.tf32.f32 %0, %1;" : "=r"(u) : "f"(f));
    return u;
}

__device__ __forceinline__ void cpasync16(float* dst, const float* src, bool pred) {
    uint32_t d = (uint32_t)__cvta_generic_to_shared(dst);
    int sz = pred ? 16 : 0;   // src-size 0 => zero-fill, no memory access
    asm volatile("cp.async.cg.shared.global [%0], [%1], 16, %2;\n"
                 :: "r"(d), "l"(src), "r"(sz));
}

__device__ __forceinline__ void mma_tf32(float* c, const uint32_t* a, const uint32_t* b) {
    asm volatile(
        "mma.sync.aligned.m16n8k8.row.col.f32.tf32.tf32.f32 "
        "{%0,%1,%2,%3}, {%4,%5,%6,%7}, {%8,%9}, {%0,%1,%2,%3};\n"
        : "+f"(c[0]), "+f"(c[1]), "+f"(c[2]), "+f"(c[3])
        : "r"(a[0]), "r"(a[1]), "r"(a[2]), "r"(a[3]), "r"(b[0]), "r"(b[1]));
}

__global__ __launch_bounds__(256, 2)
void gemm_tf32(const float* __restrict__ A, const float* __restrict__ B,
               const float* __restrict__ bias, float* __restrict__ C,
               int M, int N, int K, int lda, int ldb, int ldc,
               long long sA, long long sB, long long sC,
               float alpha, const float* __restrict__ alpha_ptr, float beta)
{
    extern __shared__ float smem[];
    float* As = smem;                    // [2][BM][ASTR]
    float* Bs = smem + 2 * BM * ASTR;    // [2][BN][ASTR]

    const float* Ab = A + (long long)blockIdx.z * sA;
    const float* Bb = B + (long long)blockIdx.z * sB;
    float*       Cb = C + (long long)blockIdx.z * sC;

    const int m0 = blockIdx.y * BM;
    const int n0 = blockIdx.x * BN;
    const int tid  = threadIdx.x;
    const int lane = tid & 31;
    const int warp = tid >> 5;
    const int wm = (warp & 1) * 64;   // warp m-offset in tile
    const int wn = (warp >> 1) * 32;  // warp n-offset in tile
    const int g  = lane >> 2;         // groupID
    const int tg = lane & 3;          // thread-in-group

    float c[4][4][4];
#pragma unroll
    for (int i = 0; i < 4; i++)
#pragma unroll
        for (int j = 0; j < 4; j++)
#pragma unroll
            for (int r = 0; r < 4; r++) c[i][j][r] = 0.f;

    const int nk = K / BK;

    // ---- tile loader (8 x cp.async.cg per thread) ----
    auto load_tile = [&](int k0, int buf) {
        float* Ad = As + buf * BM * ASTR;
        float* Bd = Bs + buf * BN * ASTR;
#pragma unroll
        for (int j = 0; j < 4; j++) {
            int cidx = tid + j * 256;          // 0..1023
            int row  = cidx >> 3;              // 0..127
            int kc   = (cidx & 7) << 2;        // 0,4,..,28
            cpasync16(Ad + row * ASTR + kc,
                      Ab + (long long)(m0 + row) * lda + k0 + kc,
                      (m0 + row) < M);
            cpasync16(Bd + row * ASTR + kc,
                      Bb + (long long)(n0 + row) * ldb + k0 + kc,
                      (n0 + row) < N);
        }
        asm volatile("cp.async.commit_group;\n");
    };

    load_tile(0, 0);

    for (int it = 0; it < nk; it++) {
        if (it + 1 < nk) {
            load_tile((it + 1) * BK, (it + 1) & 1);
            asm volatile("cp.async.wait_group 1;\n");
        } else {
            asm volatile("cp.async.wait_group 0;\n");
        }
        __syncthreads();

        const float* Ac = As + (it & 1) * BM * ASTR;
        const float* Bc = Bs + (it & 1) * BN * ASTR;

#pragma unroll
        for (int ks = 0; ks < BK; ks += 8) {
            uint32_t bf[4][2];
#pragma unroll
            for (int nt = 0; nt < 4; nt++) {
                const float* bp = Bc + (wn + nt * 8 + g) * ASTR + ks + tg;
                bf[nt][0] = f2tf(bp[0]);
                bf[nt][1] = f2tf(bp[4]);
            }
            uint32_t af[4][4];
#pragma unroll
            for (int mt = 0; mt < 4; mt++) {
                const float* ap = Ac + (wm + mt * 16 + g) * ASTR + ks + tg;
                af[mt][0] = f2tf(ap[0]);
                af[mt][1] = f2tf(ap[8 * ASTR]);
                af[mt][2] = f2tf(ap[4]);
                af[mt][3] = f2tf(ap[8 * ASTR + 4]);
            }
#pragma unroll
            for (int mt = 0; mt < 4; mt++)
#pragma unroll
                for (int nt = 0; nt < 4; nt++)
                    mma_tf32(c[mt][nt], af[mt], bf[nt]);
        }
        __syncthreads();
    }

    float aE = alpha;
    if (alpha_ptr) aE *= *alpha_ptr;

#pragma unroll
    for (int mt = 0; mt < 4; mt++) {
#pragma unroll
        for (int r = 0; r < 2; r++) {
            const int gm = m0 + wm + mt * 16 + g + r * 8;
            if (gm >= M) continue;
            float* crow = Cb + (long long)gm * ldc;
#pragma unroll
            for (int nt = 0; nt < 4; nt++) {
                const int gn = n0 + wn + nt * 8 + tg * 2;
                if (gn >= N) continue;   // gn even, N even -> gn+1 < N too
                float x = c[mt][nt][r * 2 + 0] * aE;
                float y = c[mt][nt][r * 2 + 1] * aE;
                if (bias) { x += bias[gn]; y += bias[gn + 1]; }
                if (beta != 0.f) {
                    float2 p = *(const float2*)(crow + gn);
                    x += beta * p.x; y += beta * p.y;
                }
                *(float2*)(crow + gn) = make_float2(x, y);
            }
        }
    }
}

// ---------------- heads + RMSNorm + RoPE + concat ----------------
__global__ void build_qkv(const float* __restrict__ Pq, const float* __restrict__ Pk,
                          const float* __restrict__ Pv, const float* __restrict__ Eq,
                          const float* __restrict__ Ek, const float* __restrict__ Ev,
                          const float* __restrict__ rc, const float* __restrict__ rs,
                          const float* __restrict__ nqw, const float* __restrict__ nkw,
                          const float* __restrict__ naqw, const float* __restrict__ nakw,
                          float* __restrict__ Q, float* __restrict__ K, float* __restrict__ Vt)
{
    const int s = blockIdx.x;   // 0..SEQ-1
    const int h = blockIdx.y;   // head
    const int d = threadIdx.x;  // 0..127

    const float *sq, *sk, *sv, *wq, *wk;
    if (s < S_ENC) {
        const long long off = (long long)s * DIMN + h * HD;
        sq = Eq + off; sk = Ek + off; sv = Ev + off;
        wq = naqw; wk = nakw;
    } else {
        const long long off = (long long)(s - S_ENC) * DIMN + h * HD;
        sq = Pq + off; sk = Pk + off; sv = Pv + off;
        wq = nqw; wk = nkw;
    }
    float q = sq[d], k = sk[d], v = sv[d];

    float ssq = q * q, ssk = k * k;
#pragma unroll
    for (int o = 16; o; o >>= 1) {
        ssq += __shfl_xor_sync(0xffffffffu, ssq, o);
        ssk += __shfl_xor_sync(0xffffffffu, ssk, o);
    }
    __shared__ float shq[4], shk[4];
    const int w = d >> 5;
    if ((d & 31) == 0) { shq[w] = ssq; shk[w] = ssk; }
    __syncthreads();
    const float tq = shq[0] + shq[1] + shq[2] + shq[3];
    const float tk = shk[0] + shk[1] + shk[2] + shk[3];

    const float qn = q * rsqrtf(tq * (1.0f / HD) + 1e-6f) * wq[d];
    const float kn = k * rsqrtf(tk * (1.0f / HD) + 1e-6f) * wk[d];

    const float qp = __shfl_xor_sync(0xffffffffu, qn, 1);
    const float kp = __shfl_xor_sync(0xffffffffu, kn, 1);
    const float qr = (d & 1) ? qp : -qp;
    const float kr = (d & 1) ? kp : -kp;

    const float cc = rc[(long long)s * HD + d];
    const float sn = rs[(long long)s * HD + d];

    const long long o = ((long long)h * SEQ + s) * HD + d;
    Q[o] = qn * cc + qr * sn;
    K[o] = kn * cc + kr * sn;
    Vt[((long long)h * HD + d) * SEQ + s] = v;
}

// ---------------- row softmax (in place) ----------------
__global__ void softmax_k(float* __restrict__ S, int ncols)
{
    float* r = S + (long long)blockIdx.x * ncols;
    const int tid = threadIdx.x;
    __shared__ float sh[8];

    float m = -INFINITY;
    for (int c = tid; c < ncols; c += 256) m = fmaxf(m, r[c]);
#pragma unroll
    for (int o = 16; o; o >>= 1) m = fmaxf(m, __shfl_xor_sync(0xffffffffu, m, o));
    if ((tid & 31) == 0) sh[tid >> 5] = m;
    __syncthreads();
    float bm = sh[0];
#pragma unroll
    for (int i = 1; i < 8; i++) bm = fmaxf(bm, sh[i]);
    __syncthreads();

    float sum = 0.f;
    for (int c = tid; c < ncols; c += 256) {
        float e = expf(r[c] - bm);
        r[c] = e;
        sum += e;
    }
#pragma unroll
    for (int o = 16; o; o >>= 1) sum += __shfl_xor_sync(0xffffffffu, sum, o);
    if ((tid & 31) == 0) sh[tid >> 5] = sum;
    __syncthreads();
    float bs = 0.f;
#pragma unroll
    for (int i = 0; i < 8; i++) bs += sh[i];
    const float inv = 1.0f / bs;
    for (int c = tid; c < ncols; c += 256) r[c] *= inv;
}

// ---------------- mean of V per dim (rows >= 1536 are uniform softmax) ----------------
__global__ void mean_k(const float* __restrict__ Vt, float* __restrict__ mean)
{
    const int row = blockIdx.x;       // dim index = h*HD + d, 0..3071
    const float* r = Vt + (long long)row * SEQ;
    const int tid = threadIdx.x;
    float s = 0.f;
    for (int c = tid; c < SEQ; c += 256) s += r[c];
#pragma unroll
    for (int o = 16; o; o >>= 1) s += __shfl_xor_sync(0xffffffffu, s, o);
    __shared__ float sh[8];
    if ((tid & 31) == 0) sh[tid >> 5] = s;
    __syncthreads();
    if (tid == 0) {
        float t = 0.f;
#pragma unroll
        for (int i = 0; i < 8; i++) t += sh[i];
        mean[row] = t * (1.0f / SEQ);
    }
}

// vec = mean @ Wo^T + bo  (one warp per output element)
__global__ void gemv_out(const float* __restrict__ mean, const float* __restrict__ Wo,
                         const float* __restrict__ bo, float* __restrict__ vec)
{
    const int j = blockIdx.x * 8 + (threadIdx.x >> 5);
    const int lane = threadIdx.x & 31;
    const float* w = Wo + (long long)j * DIMN;
    float s = 0.f;
    for (int d = lane; d < DIMN; d += 32) s += mean[d] * w[d];
#pragma unroll
    for (int o = 16; o; o >>= 1) s += __shfl_xor_sync(0xffffffffu, s, o);
    if (lane == 0) vec[j] = s + bo[j];
}

// broadcast vec into hid_out rows [1024, 3072)
__global__ void fill_rows(const float* __restrict__ vec, float* __restrict__ out)
{
    const long long i = (long long)blockIdx.x * 256 + threadIdx.x; // float4 index
    const float4 v = ((const float4*)vec)[i % (DIMN / 4)];
    ((float4*)out)[i] = v;
}

// ---------------- host-side launch helper ----------------
#define GEMM_SMEM ((2 * BM * ASTR + 2 * BN * ASTR) * 4)

static void gemm(const float* A, const float* B, const float* bias, float* C,
                 int M, int N, int K, int lda, int ldb, int ldc,
                 long long sA, long long sB, long long sC, int batch,
                 float alpha, const float* aptr, float beta)
{
    dim3 gdim((N + BN - 1) / BN, (M + BM - 1) / BM, batch);
    gemm_tf32<<<gdim, 256, GEMM_SMEM>>>(A, B, bias, C, M, N, K, lda, ldb, ldc,
                                        sA, sB, sC, alpha, aptr, beta);
}

extern "C" void kernel_launch(void* const* d_in, const int* in_sizes, int n_in,
                              void* d_out, int out_size)
{
    const float* hidden = (const float*)d_in[0];
    const float* enc    = (const float*)d_in[1];
    const float* rc     = (const float*)d_in[2];
    const float* rs     = (const float*)d_in[3];
    const float* Wq  = (const float*)d_in[4];
    const float* Wk  = (const float*)d_in[5];
    const float* Wv  = (const float*)d_in[6];
    const float* Wqa = (const float*)d_in[7];
    const float* Wka = (const float*)d_in[8];
    const float* Wva = (const float*)d_in[9];
    const float* Wo  = (const float*)d_in[10];
    const float* Woa = (const float*)d_in[11];
    const float* bq  = (const float*)d_in[12];
    const float* bk  = (const float*)d_in[13];
    const float* bv  = (const float*)d_in[14];
    const float* bqa = (const float*)d_in[15];
    const float* bka = (const float*)d_in[16];
    const float* bva = (const float*)d_in[17];
    const float* bo  = (const float*)d_in[18];
    const float* boa = (const float*)d_in[19];
    const float* nqw  = (const float*)d_in[20];
    const float* nkw  = (const float*)d_in[21];
    const float* naqw = (const float*)d_in[22];
    const float* nakw = (const float*)d_in[23];
    const float* qd = (const float*)d_in[24];
    const float* kd = (const float*)d_in[25];
    const float* vd = (const float*)d_in[26];
    const float* qu = (const float*)d_in[27];
    const float* ku = (const float*)d_in[28];
    const float* vu = (const float*)d_in[29];
    const float* lw = (const float*)d_in[30];

    float *Pq, *Pk, *Pv, *Eq, *Ek, *Ev, *Dt, *Q, *K, *Vt, *SA, *SB, *AO, *mean, *vec;
    cudaGetSymbolAddress((void**)&Pq, g_Pq);
    cudaGetSymbolAddress((void**)&Pk, g_Pk);
    cudaGetSymbolAddress((void**)&Pv, g_Pv);
    cudaGetSymbolAddress((void**)&Eq, g_Eq);
    cudaGetSymbolAddress((void**)&Ek, g_Ek);
    cudaGetSymbolAddress((void**)&Ev, g_Ev);
    cudaGetSymbolAddress((void**)&Dt, g_Dt);
    cudaGetSymbolAddress((void**)&Q,  g_Q);
    cudaGetSymbolAddress((void**)&K,  g_K);
    cudaGetSymbolAddress((void**)&Vt, g_Vt);
    cudaGetSymbolAddress((void**)&SA, g_SA);
    cudaGetSymbolAddress((void**)&SB, g_SB);
    cudaGetSymbolAddress((void**)&AO, g_AO);
    cudaGetSymbolAddress((void**)&mean, g_mean);
    cudaGetSymbolAddress((void**)&vec,  g_vec);

    float* out = (float*)d_out;

    cudaFuncSetAttribute(gemm_tf32, cudaFuncAttributeMaxDynamicSharedMemorySize, GEMM_SMEM);

    // 1) image-side base projections: P = hidden @ W^T + b
    gemm(hidden, Wq, bq, Pq, S_HID, DIMN, DIMN, DIMN, DIMN, DIMN, 0, 0, 0, 1, 1.f, nullptr, 0.f);
    gemm(hidden, Wk, bk, Pk, S_HID, DIMN, DIMN, DIMN, DIMN, DIMN, 0, 0, 0, 1, 1.f, nullptr, 0.f);
    gemm(hidden, Wv, bv, Pv, S_HID, DIMN, DIMN, DIMN, DIMN, DIMN, 0, 0, 0, 1, 1.f, nullptr, 0.f);

    // 2) encoder projections
    gemm(enc, Wqa, bqa, Eq, S_ENC, DIMN, DIMN, DIMN, DIMN, DIMN, 0, 0, 0, 1, 1.f, nullptr, 0.f);
    gemm(enc, Wka, bka, Ek, S_ENC, DIMN, DIMN, DIMN, DIMN, DIMN, 0, 0, 0, 1, 1.f, nullptr, 0.f);
    gemm(enc, Wva, bva, Ev, S_ENC, DIMN, DIMN, DIMN, DIMN, DIMN, 0, 0, 0, 1, 1.f, nullptr, 0.f);

    // 3) LoRA: only hidden rows [2048,3072) survive the mask; sc = lora_w[0]*ALPHA/RANK = lora_w[0]
    const float* downs[3] = {qd, kd, vd};
    const float* ups[3]   = {qu, ku, vu};
    float* Ps[3]          = {Pq, Pk, Pv};
    for (int i = 0; i < 3; i++) {
        gemm(hidden + (long long)BLOCKL * DIMN, downs[i], nullptr, Dt,
             CONDN, RANKN, DIMN, DIMN, DIMN, RANKN, 0, 0, 0, 1, 1.f, nullptr, 0.f);
        gemm(Dt, ups[i], nullptr, Ps[i] + (long long)BLOCKL * DIMN,
             CONDN, DIMN, RANKN, RANKN, RANKN, DIMN, 0, 0, 0, 1, 1.f, lw, 1.f);
    }

    // 4) heads + RMSNorm + RoPE + concat; V written transposed
    build_qkv<<<dim3(SEQ, HEADS), HD>>>(Pq, Pk, Pv, Eq, Ek, Ev, rc, rs,
                                        nqw, nkw, naqw, nakw, Q, K, Vt);

    // 5) block A: encoder queries (rows 0..511), full keys
    gemm(Q, K, nullptr, SA, S_ENC, SEQ, HD, HD, HD, SEQ,
         (long long)SEQ * HD, (long long)SEQ * HD, (long long)S_ENC * SEQ, HEADS,
         ATTN_SCALE, nullptr, 0.f);
    softmax_k<<<HEADS * S_ENC, 256>>>(SA, SEQ);
    gemm(SA, Vt, nullptr, AO, S_ENC, HD, SEQ, SEQ, SEQ, DIMN,
         (long long)S_ENC * SEQ, (long long)HD * SEQ, HD, HEADS, 1.f, nullptr, 0.f);

    // 6) block B: cond queries (rows 512..1535), keys 512..1535 only
    gemm(Q + (long long)S_ENC * HD, K + (long long)S_ENC * HD, nullptr, SB,
         CONDN, CONDN, HD, HD, HD, CONDN,
         (long long)SEQ * HD, (long long)SEQ * HD, (long long)CONDN * CONDN, HEADS,
         ATTN_SCALE, nullptr, 0.f);
    softmax_k<<<HEADS * CONDN, 256>>>(SB, CONDN);
    gemm(SB, Vt + S_ENC, nullptr, AO + (long long)S_ENC * DIMN,
         CONDN, HD, CONDN, CONDN, SEQ, DIMN,
         (long long)CONDN * CONDN, (long long)HD * SEQ, HD, HEADS, 1.f, nullptr, 0.f);

    // 7) fully-masked rows -> uniform softmax -> mean of V; out-proj of that row ONCE
    mean_k<<<DIMN, 256>>>(Vt, mean);
    gemv_out<<<DIMN / 8, 256>>>(mean, Wo, bo, vec);

    // 8) output projections
    //    hid_out rows 0..1023 = AO rows 512..1535 @ Wo^T + bo
    gemm(AO + (long long)S_ENC * DIMN, Wo, bo, out,
         CONDN, DIMN, DIMN, DIMN, DIMN, DIMN, 0, 0, 0, 1, 1.f, nullptr, 0.f);
    //    hid_out rows 1024..3071 = broadcast of vec
    fill_rows<<<(NROWS_C * (DIMN / 4)) / 256, 256>>>(vec, out + (long long)CONDN * DIMN);
    //    enc_out = AO rows 0..511 @ Woa^T + boa
    gemm(AO, Woa, boa, out + (long long)S_HID * DIMN,
         S_ENC, DIMN, DIMN, DIMN, DIMN, DIMN, 0, 0, 0, 1, 1.f, nullptr, 0.f);
}

// round 3
// speedup vs baseline: 3.1485x; 1.1755x over previous
#include <cuda_runtime.h>
#include <math.h>
#include <stdint.h>

// ---------------- problem constants ----------------
#define DIMN   3072
#define HEADS  24
#define HD     128
#define S_HID  3072
#define S_ENC  512
#define SEQ    3584          // S_ENC + S_HID
#define CONDN  1024
#define RANKN  64
#define BLOCKL 2048          // S_HID - CONDN
#define NROWS_C (SEQ - S_ENC - CONDN)   // 2048 fully-masked query rows
#define KSPLIT 8             // split-K for LoRA down-proj
static const float ATTN_SCALE = 0.08838834764831843f; // 1/sqrt(128)

// ---------------- device scratch (no allocs allowed) ----------------
__device__ float g_Pq[(size_t)S_HID * DIMN];
__device__ float g_Pk[(size_t)S_HID * DIMN];
__device__ float g_Pv[(size_t)S_HID * DIMN];
__device__ float g_Eq[(size_t)S_ENC * DIMN];
__device__ float g_Ek[(size_t)S_ENC * DIMN];
__device__ float g_Ev[(size_t)S_ENC * DIMN];
__device__ float g_Dt[(size_t)CONDN * RANKN];
__device__ float g_DtP[(size_t)KSPLIT * CONDN * RANKN];  // split-K partials
__device__ float g_Q [(size_t)HEADS * SEQ * HD];
__device__ float g_K [(size_t)HEADS * SEQ * HD];
__device__ float g_Vt[(size_t)HEADS * HD * SEQ];     // V transposed: [h][d][s]
__device__ float g_SA[(size_t)HEADS * S_ENC * SEQ];   // encoder-query scores
__device__ float g_SB[(size_t)HEADS * CONDN * CONDN]; // cond-block scores
__device__ float g_AO[(size_t)(S_ENC + CONDN) * DIMN];// attention out rows 0..1535
__device__ float g_mean[DIMN];                        // mean of V per dim
__device__ float g_vec [DIMN];                        // mean @ Wo^T + bo

// ---------------- tf32 tensor-core GEMM ----------------
// C = alpha * A[M,K] * B[N,K]^T (+bias, +beta*C).  A,B row-major, leading dims
// lda/ldb; batch via blockIdx.z with strides sA/sB/sC (element strides, so the
// same mechanism implements split-K chunks).
// 128x128x16 tile, 256 threads (8 warps, warp tile 64x32), 5-stage cp.async.
#define BM 128
#define BN 128
#define BK 16
#define STAGES 5
#define PF 4      // prefetch depth = STAGES-1
#define ASTR 20   // smem row stride (floats): g*20+tg mod 32 distinct per lane

__device__ __forceinline__ uint32_t f2tf(float f) {
    uint32_t u;
    asm("cvt.rna.tf32.f32 %0, %1;" : "=r"(u) : "f"(f));
    return u;
}

__device__ __forceinline__ void cpasync16(float* dst, const float* src, bool pred) {
    uint32_t d = (uint32_t)__cvta_generic_to_shared(dst);
    int sz = pred ? 16 : 0;   // src-size 0 => zero-fill, no memory access
    asm volatile("cp.async.cg.shared.global [%0], [%1], 16, %2;\n"
                 :: "r"(d), "l"(src), "r"(sz));
}

__device__ __forceinline__ void mma_tf32(float* c, const uint32_t* a, const uint32_t* b) {
    asm volatile(
        "mma.sync.aligned.m16n8k8.row.col.f32.tf32.tf32.f32 "
        "{%0,%1,%2,%3}, {%4,%5,%6,%7}, {%8,%9}, {%0,%1,%2,%3};\n"
        : "+f"(c[0]), "+f"(c[1]), "+f"(c[2]), "+f"(c[3])
        : "r"(a[0]), "r"(a[1]), "r"(a[2]), "r"(a[3]), "r"(b[0]), "r"(b[1]));
}

__global__ __launch_bounds__(256, 2)
void gemm_tf32(const float* __restrict__ A, const float* __restrict__ B,
               const float* __restrict__ bias, float* __restrict__ C,
               int M, int N, int K, int lda, int ldb, int ldc,
               long long sA, long long sB, long long sC,
               float alpha, const float* __restrict__ alpha_ptr, float beta)
{
    extern __shared__ float smem[];
    float* As = smem;                          // [STAGES][BM][ASTR]
    float* Bs = smem + STAGES * BM * ASTR;     // [STAGES][BN][ASTR]

    const float* Ab = A + (long long)blockIdx.z * sA;
    const float* Bb = B + (long long)blockIdx.z * sB;
    float*       Cb = C + (long long)blockIdx.z * sC;

    const int m0 = blockIdx.y * BM;
    const int n0 = blockIdx.x * BN;
    const int tid  = threadIdx.x;
    const int lane = tid & 31;
    const int warp = tid >> 5;
    const int wm = (warp & 1) * 64;   // warp m-offset in tile
    const int wn = (warp >> 1) * 32;  // warp n-offset in tile
    const int g  = lane >> 2;         // groupID
    const int tg = lane & 3;          // thread-in-group

    float c[4][4][4];
#pragma unroll
    for (int i = 0; i < 4; i++)
#pragma unroll
        for (int j = 0; j < 4; j++)
#pragma unroll
            for (int r = 0; r < 4; r++) c[i][j][r] = 0.f;

    const int nk = K / BK;

    // per-stage loads: A 128x16 floats + B 128x16 floats; 2 cp.async.16 each
    const int lrow = tid >> 2;              // 0..63
    const int lkc  = (tid & 3) << 2;        // 0,4,8,12

    auto load_tile = [&](int k0, int buf) {
        float* Ad = As + buf * BM * ASTR;
        float* Bd = Bs + buf * BN * ASTR;
#pragma unroll
        for (int j = 0; j < 2; j++) {
            const int row = lrow + j * 64;
            cpasync16(Ad + row * ASTR + lkc,
                      Ab + (long long)(m0 + row) * lda + k0 + lkc,
                      (m0 + row) < M);
            cpasync16(Bd + row * ASTR + lkc,
                      Bb + (long long)(n0 + row) * ldb + k0 + lkc,
                      (n0 + row) < N);
        }
        asm volatile("cp.async.commit_group;\n");
    };

    // prologue: prefetch PF stages (commit empty groups if nk < PF)
    for (int s = 0; s < PF; s++) {
        if (s < nk) load_tile(s * BK, s);
        else        asm volatile("cp.async.commit_group;\n");
    }

    for (int it = 0; it < nk; it++) {
        if (it + PF < nk) load_tile((it + PF) * BK, (it + PF) % STAGES);
        else              asm volatile("cp.async.commit_group;\n");
        asm volatile("cp.async.wait_group %0;\n" :: "n"(PF));
        __syncthreads();

        const int buf = it % STAGES;
        const float* Ac = As + buf * BM * ASTR;
        const float* Bc = Bs + buf * BN * ASTR;

#pragma unroll
        for (int ks = 0; ks < BK; ks += 8) {
            uint32_t bf[4][2];
#pragma unroll
            for (int nt = 0; nt < 4; nt++) {
                const float* bp = Bc + (wn + nt * 8 + g) * ASTR + ks + tg;
                bf[nt][0] = f2tf(bp[0]);
                bf[nt][1] = f2tf(bp[4]);
            }
            uint32_t af[4][4];
#pragma unroll
            for (int mt = 0; mt < 4; mt++) {
                const float* ap = Ac + (wm + mt * 16 + g) * ASTR + ks + tg;
                af[mt][0] = f2tf(ap[0]);
                af[mt][1] = f2tf(ap[8 * ASTR]);
                af[mt][2] = f2tf(ap[4]);
                af[mt][3] = f2tf(ap[8 * ASTR + 4]);
            }
#pragma unroll
            for (int mt = 0; mt < 4; mt++)
#pragma unroll
                for (int nt = 0; nt < 4; nt++)
                    mma_tf32(c[mt][nt], af[mt], bf[nt]);
        }
        __syncthreads();
    }

    float aE = alpha;
    if (alpha_ptr) aE *= *alpha_ptr;

#pragma unroll
    for (int mt = 0; mt < 4; mt++) {
#pragma unroll
        for (int r = 0; r < 2; r++) {
            const int gm = m0 + wm + mt * 16 + g + r * 8;
            if (gm >= M) continue;
            float* crow = Cb + (long long)gm * ldc;
#pragma unroll
            for (int nt = 0; nt < 4; nt++) {
                const int gn = n0 + wn + nt * 8 + tg * 2;
                if (gn >= N) continue;   // gn even, N even -> gn+1 < N too
                float x = c[mt][nt][r * 2 + 0] * aE;
                float y = c[mt][nt][r * 2 + 1] * aE;
                if (bias) { x += bias[gn]; y += bias[gn + 1]; }
                if (beta != 0.f) {
                    float2 p = *(const float2*)(crow + gn);
                    x += beta * p.x; y += beta * p.y;
                }
                *(float2*)(crow + gn) = make_float2(x, y);
            }
        }
    }
}

// ---------------- heads + RMSNorm + RoPE + concat ----------------
__global__ void build_qkv(const float* __restrict__ Pq, const float* __restrict__ Pk,
                          const float* __restrict__ Pv, const float* __restrict__ Eq,
                          const float* __restrict__ Ek, const float* __restrict__ Ev,
                          const float* __restrict__ rc, const float* __restrict__ rs,
                          const float* __restrict__ nqw, const float* __restrict__ nkw,
                          const float* __restrict__ naqw, const float* __restrict__ nakw,
                          float* __restrict__ Q, float* __restrict__ K, float* __restrict__ Vt)
{
    const int s = blockIdx.x;   // 0..SEQ-1
    const int h = blockIdx.y;   // head
    const int d = threadIdx.x;  // 0..127

    const float *sq, *sk, *sv, *wq, *wk;
    if (s < S_ENC) {
        const long long off = (long long)s * DIMN + h * HD;
        sq = Eq + off; sk = Ek + off; sv = Ev + off;
        wq = naqw; wk = nakw;
    } else {
        const long long off = (long long)(s - S_ENC) * DIMN + h * HD;
        sq = Pq + off; sk = Pk + off; sv = Pv + off;
        wq = nqw; wk = nkw;
    }
    float q = sq[d], k = sk[d], v = sv[d];

    float ssq = q * q, ssk = k * k;
#pragma unroll
    for (int o = 16; o; o >>= 1) {
        ssq += __shfl_xor_sync(0xffffffffu, ssq, o);
        ssk += __shfl_xor_sync(0xffffffffu, ssk, o);
    }
    __shared__ float shq[4], shk[4];
    const int w = d >> 5;
    if ((d & 31) == 0) { shq[w] = ssq; shk[w] = ssk; }
    __syncthreads();
    const float tq = shq[0] + shq[1] + shq[2] + shq[3];
    const float tk = shk[0] + shk[1] + shk[2] + shk[3];

    const float qn = q * rsqrtf(tq * (1.0f / HD) + 1e-6f) * wq[d];
    const float kn = k * rsqrtf(tk * (1.0f / HD) + 1e-6f) * wk[d];

    const float qp = __shfl_xor_sync(0xffffffffu, qn, 1);
    const float kp = __shfl_xor_sync(0xffffffffu, kn, 1);
    const float qr = (d & 1) ? qp : -qp;
    const float kr = (d & 1) ? kp : -kp;

    const float cc = rc[(long long)s * HD + d];
    const float sn = rs[(long long)s * HD + d];

    const long long o = ((long long)h * SEQ + s) * HD + d;
    Q[o] = qn * cc + qr * sn;
    K[o] = kn * cc + kr * sn;
    Vt[((long long)h * HD + d) * SEQ + s] = v;
}

// ---------------- row softmax (in place) ----------------
__global__ void softmax_k(float* __restrict__ S, int ncols)
{
    float* r = S + (long long)blockIdx.x * ncols;
    const int tid = threadIdx.x;
    __shared__ float sh[8];

    float m = -INFINITY;
    for (int c = tid; c < ncols; c += 256) m = fmaxf(m, r[c]);
#pragma unroll
    for (int o = 16; o; o >>= 1) m = fmaxf(m, __shfl_xor_sync(0xffffffffu, m, o));
    if ((tid & 31) == 0) sh[tid >> 5] = m;
    __syncthreads();
    float bm = sh[0];
#pragma unroll
    for (int i = 1; i < 8; i++) bm = fmaxf(bm, sh[i]);
    __syncthreads();

    float sum = 0.f;
    for (int c = tid; c < ncols; c += 256) {
        float e = expf(r[c] - bm);
        r[c] = e;
        sum += e;
    }
#pragma unroll
    for (int o = 16; o; o >>= 1) sum += __shfl_xor_sync(0xffffffffu, sum, o);
    if ((tid & 31) == 0) sh[tid >> 5] = sum;
    __syncthreads();
    float bs = 0.f;
#pragma unroll
    for (int i = 0; i < 8; i++) bs += sh[i];
    const float inv = 1.0f / bs;
    for (int c = tid; c < ncols; c += 256) r[c] *= inv;
}

// ---------------- mean of V per dim (rows >= 1536 are uniform softmax) ----------------
__global__ void mean_k(const float* __restrict__ Vt, float* __restrict__ mean)
{
    const int row = blockIdx.x;       // dim index = h*HD + d, 0..3071
    const float* r = Vt + (long long)row * SEQ;
    const int tid = threadIdx.x;
    float s = 0.f;
    for (int c = tid; c < SEQ; c += 256) s += r[c];
#pragma unroll
    for (int o = 16; o; o >>= 1) s += __shfl_xor_sync(0xffffffffu, s, o);
    __shared__ float sh[8];
    if ((tid & 31) == 0) sh[tid >> 5] = s;
    __syncthreads();
    if (tid == 0) {
        float t = 0.f;
#pragma unroll
        for (int i = 0; i < 8; i++) t += sh[i];
        mean[row] = t * (1.0f / SEQ);
    }
}

// vec = mean @ Wo^T + bo  (one warp per output element)
__global__ void gemv_out(const float* __restrict__ mean, const float* __restrict__ Wo,
                         const float* __restrict__ bo, float* __restrict__ vec)
{
    const int j = blockIdx.x * 8 + (threadIdx.x >> 5);
    const int lane = threadIdx.x & 31;
    const float* w = Wo + (long long)j * DIMN;
    float s = 0.f;
    for (int d = lane; d < DIMN; d += 32) s += mean[d] * w[d];
#pragma unroll
    for (int o = 16; o; o >>= 1) s += __shfl_xor_sync(0xffffffffu, s, o);
    if (lane == 0) vec[j] = s + bo[j];
}

// broadcast vec into hid_out rows [1024, 3072)
__global__ void fill_rows(const float* __restrict__ vec, float* __restrict__ out)
{
    const long long i = (long long)blockIdx.x * 256 + threadIdx.x; // float4 index
    const float4 v = ((const float4*)vec)[i % (DIMN / 4)];
    ((float4*)out)[i] = v;
}

// sum split-K partials: Dt[i] = sum_z DtP[z][i]
__global__ void reduce_splitk(const float* __restrict__ P, float* __restrict__ D)
{
    const int i = blockIdx.x * 256 + threadIdx.x;
    float s = 0.f;
#pragma unroll
    for (int z = 0; z < KSPLIT; z++) s += P[(size_t)z * CONDN * RANKN + i];
    D[i] = s;
}

// ---------------- host-side launch helper ----------------
#define GEMM_SMEM (STAGES * (BM * ASTR + BN * ASTR) * 4)

static void gemm(const float* A, const float* B, const float* bias, float* C,
                 int M, int N, int K, int lda, int ldb, int ldc,
                 long long sA, long long sB, long long sC, int batch,
                 float alpha, const float* aptr, float beta)
{
    dim3 gdim((N + BN - 1) / BN, (M + BM - 1) / BM, batch);
    gemm_tf32<<<gdim, 256, GEMM_SMEM>>>(A, B, bias, C, M, N, K, lda, ldb, ldc,
                                        sA, sB, sC, alpha, aptr, beta);
}

extern "C" void kernel_launch(void* const* d_in, const int* in_sizes, int n_in,
                              void* d_out, int out_size)
{
    const float* hidden = (const float*)d_in[0];
    const float* enc    = (const float*)d_in[1];
    const float* rc     = (const float*)d_in[2];
    const float* rs     = (const float*)d_in[3];
    const float* Wq  = (const float*)d_in[4];
    const float* Wk  = (const float*)d_in[5];
    const float* Wv  = (const float*)d_in[6];
    const float* Wqa = (const float*)d_in[7];
    const float* Wka = (const float*)d_in[8];
    const float* Wva = (const float*)d_in[9];
    const float* Wo  = (const float*)d_in[10];
    const float* Woa = (const float*)d_in[11];
    const float* bq  = (const float*)d_in[12];
    const float* bk  = (const float*)d_in[13];
    const float* bv  = (const float*)d_in[14];
    const float* bqa = (const float*)d_in[15];
    const float* bka = (const float*)d_in[16];
    const float* bva = (const float*)d_in[17];
    const float* bo  = (const float*)d_in[18];
    const float* boa = (const float*)d_in[19];
    const float* nqw  = (const float*)d_in[20];
    const float* nkw  = (const float*)d_in[21];
    const float* naqw = (const float*)d_in[22];
    const float* nakw = (const float*)d_in[23];
    const float* qd = (const float*)d_in[24];
    const float* kd = (const float*)d_in[25];
    const float* vd = (const float*)d_in[26];
    const float* qu = (const float*)d_in[27];
    const float* ku = (const float*)d_in[28];
    const float* vu = (const float*)d_in[29];
    const float* lw = (const float*)d_in[30];

    float *Pq, *Pk, *Pv, *Eq, *Ek, *Ev, *Dt, *DtP, *Q, *K, *Vt, *SA, *SB, *AO, *mean, *vec;
    cudaGetSymbolAddress((void**)&Pq, g_Pq);
    cudaGetSymbolAddress((void**)&Pk, g_Pk);
    cudaGetSymbolAddress((void**)&Pv, g_Pv);
    cudaGetSymbolAddress((void**)&Eq, g_Eq);
    cudaGetSymbolAddress((void**)&Ek, g_Ek);
    cudaGetSymbolAddress((void**)&Ev, g_Ev);
    cudaGetSymbolAddress((void**)&Dt, g_Dt);
    cudaGetSymbolAddress((void**)&DtP, g_DtP);
    cudaGetSymbolAddress((void**)&Q,  g_Q);
    cudaGetSymbolAddress((void**)&K,  g_K);
    cudaGetSymbolAddress((void**)&Vt, g_Vt);
    cudaGetSymbolAddress((void**)&SA, g_SA);
    cudaGetSymbolAddress((void**)&SB, g_SB);
    cudaGetSymbolAddress((void**)&AO, g_AO);
    cudaGetSymbolAddress((void**)&mean, g_mean);
    cudaGetSymbolAddress((void**)&vec,  g_vec);

    float* out = (float*)d_out;

    cudaFuncSetAttribute(gemm_tf32, cudaFuncAttributeMaxDynamicSharedMemorySize, GEMM_SMEM);

    // 1) image-side base projections: P = hidden @ W^T + b
    gemm(hidden, Wq, bq, Pq, S_HID, DIMN, DIMN, DIMN, DIMN, DIMN, 0, 0, 0, 1, 1.f, nullptr, 0.f);
    gemm(hidden, Wk, bk, Pk, S_HID, DIMN, DIMN, DIMN, DIMN, DIMN, 0, 0, 0, 1, 1.f, nullptr, 0.f);
    gemm(hidden, Wv, bv, Pv, S_HID, DIMN, DIMN, DIMN, DIMN, DIMN, 0, 0, 0, 1, 1.f, nullptr, 0.f);

    // 2) encoder projections
    gemm(enc, Wqa, bqa, Eq, S_ENC, DIMN, DIMN, DIMN, DIMN, DIMN, 0, 0, 0, 1, 1.f, nullptr, 0.f);
    gemm(enc, Wka, bka, Ek, S_ENC, DIMN, DIMN, DIMN, DIMN, DIMN, 0, 0, 0, 1, 1.f, nullptr, 0.f);
    gemm(enc, Wva, bva, Ev, S_ENC, DIMN, DIMN, DIMN, DIMN, DIMN, 0, 0, 0, 1, 1.f, nullptr, 0.f);

    // 3) LoRA: only hidden rows [2048,3072) survive the mask; sc = lora_w[0]*ALPHA/RANK = lora_w[0]
    //    down-proj uses split-K=8 via the batch stride mechanism (K chunks of 384)
    const float* downs[3] = {qd, kd, vd};
    const float* ups[3]   = {qu, ku, vu};
    float* Ps[3]          = {Pq, Pk, Pv};
    for (int i = 0; i < 3; i++) {
        gemm(hidden + (long long)BLOCKL * DIMN, downs[i], nullptr, DtP,
             CONDN, RANKN, DIMN / KSPLIT, DIMN, DIMN, RANKN,
             DIMN / KSPLIT, DIMN / KSPLIT, (long long)CONDN * RANKN, KSPLIT,
             1.f, nullptr, 0.f);
        reduce_splitk<<<(CONDN * RANKN) / 256, 256>>>(DtP, Dt);
        gemm(Dt, ups[i], nullptr, Ps[i] + (long long)BLOCKL * DIMN,
             CONDN, DIMN, RANKN, RANKN, RANKN, DIMN, 0, 0, 0, 1, 1.f, lw, 1.f);
    }

    // 4) heads + RMSNorm + RoPE + concat; V written transposed
    build_qkv<<<dim3(SEQ, HEADS), HD>>>(Pq, Pk, Pv, Eq, Ek, Ev, rc, rs,
                                        nqw, nkw, naqw, nakw, Q, K, Vt);

    // 5) block A: encoder queries (rows 0..511), full keys
    gemm(Q, K, nullptr, SA, S_ENC, SEQ, HD, HD, HD, SEQ,
         (long long)SEQ * HD, (long long)SEQ * HD, (long long)S_ENC * SEQ, HEADS,
         ATTN_SCALE, nullptr, 0.f);
    softmax_k<<<HEADS * S_ENC, 256>>>(SA, SEQ);
    gemm(SA, Vt, nullptr, AO, S_ENC, HD, SEQ, SEQ, SEQ, DIMN,
         (long long)S_ENC * SEQ, (long long)HD * SEQ, HD, HEADS, 1.f, nullptr, 0.f);

    // 6) block B: cond queries (rows 512..1535), keys 512..1535 only
    gemm(Q + (long long)S_ENC * HD, K + (long long)S_ENC * HD, nullptr, SB,
         CONDN, CONDN, HD, HD, HD, CONDN,
         (long long)SEQ * HD, (long long)SEQ * HD, (long long)CONDN * CONDN, HEADS,
         ATTN_SCALE, nullptr, 0.f);
    softmax_k<<<HEADS * CONDN, 256>>>(SB, CONDN);
    gemm(SB, Vt + S_ENC, nullptr, AO + (long long)S_ENC * DIMN,
         CONDN, HD, CONDN, CONDN, SEQ, DIMN,
         (long long)CONDN * CONDN, (long long)HD * SEQ, HD, HEADS, 1.f, nullptr, 0.f);

    // 7) fully-masked rows -> uniform softmax -> mean of V; out-proj of that row ONCE
    mean_k<<<DIMN, 256>>>(Vt, mean);
    gemv_out<<<DIMN / 8, 256>>>(mean, Wo, bo, vec);

    // 8) output projections
    //    hid_out rows 0..1023 = AO rows 512..1535 @ Wo^T + bo
    gemm(AO + (long long)S_ENC * DIMN, Wo, bo, out,
         CONDN, DIMN, DIMN, DIMN, DIMN, DIMN, 0, 0, 0, 1, 1.f, nullptr, 0.f);
    //    hid_out rows 1024..3071 = broadcast of vec
    fill_rows<<<(NROWS_C * (DIMN / 4)) / 256, 256>>>(vec, out + (long long)CONDN * DIMN);
    //    enc_out = AO rows 0..511 @ Woa^T + boa
    gemm(AO, Woa, boa, out + (long long)S_HID * DIMN,
         S_ENC, DIMN, DIMN, DIMN, DIMN, DIMN, 0, 0, 0, 1, 1.f, nullptr, 0.f);
}

// round 4
// speedup vs baseline: 3.2834x; 1.0428x over previous
#include <cuda_runtime.h>
#include <math.h>
#include <stdint.h>

// ---------------- problem constants ----------------
#define DIMN   3072
#define HEADS  24
#define HD     128
#define S_HID  3072
#define S_ENC  512
#define SEQ    3584          // S_ENC + S_HID
#define CONDN  1024
#define RANKN  64
#define BLOCKL 2048          // S_HID - CONDN
#define NROWS_C (SEQ - S_ENC - CONDN)   // 2048 fully-masked query rows
#define KSPLIT 16            // split-K for LoRA down-proj
static const float ATTN_SCALE = 0.08838834764831843f; // 1/sqrt(128)

// ---------------- device scratch (no allocs allowed) ----------------
__device__ float g_Pq[(size_t)S_HID * DIMN];
__device__ float g_Pk[(size_t)S_HID * DIMN];
__device__ float g_Pv[(size_t)S_HID * DIMN];
__device__ float g_Eq[(size_t)S_ENC * DIMN];
__device__ float g_Ek[(size_t)S_ENC * DIMN];
__device__ float g_Ev[(size_t)S_ENC * DIMN];
__device__ float g_Dt[(size_t)CONDN * RANKN];
__device__ float g_DtP[(size_t)KSPLIT * CONDN * RANKN];  // split-K partials
__device__ float g_Q [(size_t)HEADS * SEQ * HD];
__device__ float g_K [(size_t)HEADS * SEQ * HD];
__device__ float g_Vt[(size_t)HEADS * HD * SEQ];     // V transposed: [h][d][s]
__device__ float g_SA[(size_t)HEADS * S_ENC * SEQ];   // encoder-query scores
__device__ float g_SB[(size_t)HEADS * CONDN * CONDN]; // cond-block scores
__device__ float g_AO[(size_t)(S_ENC + CONDN) * DIMN];// attention out rows 0..1535
__device__ float g_mean[DIMN];                        // mean of V per dim
__device__ float g_vec [DIMN];                        // mean @ Wo^T + bo

// ---------------- tf32 tensor-core GEMM (templated tile config) ----------------
// C = alpha * A[M,K] * B[N,K]^T (+bias, +beta*C).  A,B row-major, leading dims
// lda/ldb; batch via blockIdx.z with strides sA/sB/sC (also used for split-K).
// BIG  config: 128x128 tile, 256 thr (8 warps, warp tile 64x32), 4-stage cp.async
// SMALL config:  64x64 tile, 128 thr (4 warps, warp tile 32x32), 6-stage cp.async
#define BK 16
#define ASTR 20   // smem row stride (floats): g*20+tg mod 32 distinct per lane

__device__ __forceinline__ uint32_t f2tf(float f) {
    uint32_t u;
    asm("cvt.rna.tf32.f32 %0, %1;" : "=r"(u) : "f"(f));
    return u;
}

__device__ __forceinline__ void cpasync16(float* dst, const float* src, bool pred) {
    uint32_t d = (uint32_t)__cvta_generic_to_shared(dst);
    int sz = pred ? 16 : 0;   // src-size 0 => zero-fill, no memory access
    asm volatile("cp.async.cg.shared.global [%0], [%1], 16, %2;\n"
                 :: "r"(d), "l"(src), "r"(sz));
}

__device__ __forceinline__ void mma_tf32(float* c, const uint32_t* a, const uint32_t* b) {
    asm volatile(
        "mma.sync.aligned.m16n8k8.row.col.f32.tf32.tf32.f32 "
        "{%0,%1,%2,%3}, {%4,%5,%6,%7}, {%8,%9}, {%0,%1,%2,%3};\n"
        : "+f"(c[0]), "+f"(c[1]), "+f"(c[2]), "+f"(c[3])
        : "r"(a[0]), "r"(a[1]), "r"(a[2]), "r"(a[3]), "r"(b[0]), "r"(b[1]));
}

template <int TBM, int TBN, int THREADS, int NSTAGE, int MT, int OCC>
__global__ __launch_bounds__(THREADS, OCC)
void gemm_tf32(const float* __restrict__ A, const float* __restrict__ B,
               const float* __restrict__ bias, float* __restrict__ C,
               int M, int N, int K, int lda, int ldb, int ldc,
               long long sA, long long sB, long long sC,
               float alpha, const float* __restrict__ alpha_ptr, float beta)
{
    constexpr int PF = NSTAGE - 1;
    extern __shared__ float smem[];
    float* As = smem;                          // [NSTAGE][TBM][ASTR]
    float* Bs = smem + NSTAGE * TBM * ASTR;    // [NSTAGE][TBN][ASTR]

    const float* Ab = A + (long long)blockIdx.z * sA;
    const float* Bb = B + (long long)blockIdx.z * sB;
    float*       Cb = C + (long long)blockIdx.z * sC;

    const int m0 = blockIdx.y * TBM;
    const int n0 = blockIdx.x * TBN;
    const int tid  = threadIdx.x;
    const int lane = tid & 31;
    const int warp = tid >> 5;
    const int wm = (warp & 1) * (MT * 16);  // 2 m-warps
    const int wn = (warp >> 1) * 32;        // TBN/32 n-warps
    const int g  = lane >> 2;               // groupID
    const int tg = lane & 3;                // thread-in-group

    float c[MT][4][4];
#pragma unroll
    for (int i = 0; i < MT; i++)
#pragma unroll
        for (int j = 0; j < 4; j++)
#pragma unroll
            for (int r = 0; r < 4; r++) c[i][j][r] = 0.f;

    const int nk = K / BK;

    // per-stage loads: TBM x 16 A floats + TBN x 16 B floats, 16B chunks
    const int lrow = tid >> 2;              // 0..THREADS/4-1
    const int lkc  = (tid & 3) << 2;        // 0,4,8,12
    constexpr int RJUMP = THREADS / 4;      // rows covered per pass

    auto load_tile = [&](int k0, int buf) {
        float* Ad = As + buf * TBM * ASTR;
        float* Bd = Bs + buf * TBN * ASTR;
#pragma unroll
        for (int j = 0; j < TBM / RJUMP; j++) {
            const int row = lrow + j * RJUMP;
            cpasync16(Ad + row * ASTR + lkc,
                      Ab + (long long)(m0 + row) * lda + k0 + lkc,
                      (m0 + row) < M);
        }
#pragma unroll
        for (int j = 0; j < TBN / RJUMP; j++) {
            const int row = lrow + j * RJUMP;
            cpasync16(Bd + row * ASTR + lkc,
                      Bb + (long long)(n0 + row) * ldb + k0 + lkc,
                      (n0 + row) < N);
        }
        asm volatile("cp.async.commit_group;\n");
    };

    // prologue: prefetch PF stages (commit empty groups if nk < PF)
    for (int s = 0; s < PF; s++) {
        if (s < nk) load_tile(s * BK, s);
        else        asm volatile("cp.async.commit_group;\n");
    }

    for (int it = 0; it < nk; it++) {
        if (it + PF < nk) load_tile((it + PF) * BK, (it + PF) % NSTAGE);
        else              asm volatile("cp.async.commit_group;\n");
        asm volatile("cp.async.wait_group %0;\n" :: "n"(PF));
        __syncthreads();

        const int buf = it % NSTAGE;
        const float* Ac = As + buf * TBM * ASTR;
        const float* Bc = Bs + buf * TBN * ASTR;

#pragma unroll
        for (int ks = 0; ks < BK; ks += 8) {
            uint32_t bf[4][2];
#pragma unroll
            for (int nt = 0; nt < 4; nt++) {
                const float* bp = Bc + (wn + nt * 8 + g) * ASTR + ks + tg;
                bf[nt][0] = f2tf(bp[0]);
                bf[nt][1] = f2tf(bp[4]);
            }
            uint32_t af[MT][4];
#pragma unroll
            for (int mt = 0; mt < MT; mt++) {
                const float* ap = Ac + (wm + mt * 16 + g) * ASTR + ks + tg;
                af[mt][0] = f2tf(ap[0]);
                af[mt][1] = f2tf(ap[8 * ASTR]);
                af[mt][2] = f2tf(ap[4]);
                af[mt][3] = f2tf(ap[8 * ASTR + 4]);
            }
#pragma unroll
            for (int mt = 0; mt < MT; mt++)
#pragma unroll
                for (int nt = 0; nt < 4; nt++)
                    mma_tf32(c[mt][nt], af[mt], bf[nt]);
        }
        __syncthreads();
    }

    float aE = alpha;
    if (alpha_ptr) aE *= *alpha_ptr;

#pragma unroll
    for (int mt = 0; mt < MT; mt++) {
#pragma unroll
        for (int r = 0; r < 2; r++) {
            const int gm = m0 + wm + mt * 16 + g + r * 8;
            if (gm >= M) continue;
            float* crow = Cb + (long long)gm * ldc;
#pragma unroll
            for (int nt = 0; nt < 4; nt++) {
                const int gn = n0 + wn + nt * 8 + tg * 2;
                if (gn >= N) continue;   // gn even, N even -> gn+1 < N too
                float x = c[mt][nt][r * 2 + 0] * aE;
                float y = c[mt][nt][r * 2 + 1] * aE;
                if (bias) { x += bias[gn]; y += bias[gn + 1]; }
                if (beta != 0.f) {
                    float2 p = *(const float2*)(crow + gn);
                    x += beta * p.x; y += beta * p.y;
                }
                *(float2*)(crow + gn) = make_float2(x, y);
            }
        }
    }
}

// instantiations
#define BIG_ARGS   128, 128, 256, 4, 4, 2
#define SMALL_ARGS  64,  64, 128, 6, 2, 3
#define BIG_SMEM   (4 * (128 + 128) * ASTR * 4)
#define SMALL_SMEM (6 * ( 64 +  64) * ASTR * 4)

// ---------------- heads + RMSNorm + RoPE + concat ----------------
__global__ void build_qkv(const float* __restrict__ Pq, const float* __restrict__ Pk,
                          const float* __restrict__ Pv, const float* __restrict__ Eq,
                          const float* __restrict__ Ek, const float* __restrict__ Ev,
                          const float* __restrict__ rc, const float* __restrict__ rs,
                          const float* __restrict__ nqw, const float* __restrict__ nkw,
                          const float* __restrict__ naqw, const float* __restrict__ nakw,
                          float* __restrict__ Q, float* __restrict__ K, float* __restrict__ Vt)
{
    const int s = blockIdx.x;   // 0..SEQ-1
    const int h = blockIdx.y;   // head
    const int d = threadIdx.x;  // 0..127

    const float *sq, *sk, *sv, *wq, *wk;
    if (s < S_ENC) {
        const long long off = (long long)s * DIMN + h * HD;
        sq = Eq + off; sk = Ek + off; sv = Ev + off;
        wq = naqw; wk = nakw;
    } else {
        const long long off = (long long)(s - S_ENC) * DIMN + h * HD;
        sq = Pq + off; sk = Pk + off; sv = Pv + off;
        wq = nqw; wk = nkw;
    }
    float q = sq[d], k = sk[d], v = sv[d];

    float ssq = q * q, ssk = k * k;
#pragma unroll
    for (int o = 16; o; o >>= 1) {
        ssq += __shfl_xor_sync(0xffffffffu, ssq, o);
        ssk += __shfl_xor_sync(0xffffffffu, ssk, o);
    }
    __shared__ float shq[4], shk[4];
    const int w = d >> 5;
    if ((d & 31) == 0) { shq[w] = ssq; shk[w] = ssk; }
    __syncthreads();
    const float tq = shq[0] + shq[1] + shq[2] + shq[3];
    const float tk = shk[0] + shk[1] + shk[2] + shk[3];

    const float qn = q * rsqrtf(tq * (1.0f / HD) + 1e-6f) * wq[d];
    const float kn = k * rsqrtf(tk * (1.0f / HD) + 1e-6f) * wk[d];

    const float qp = __shfl_xor_sync(0xffffffffu, qn, 1);
    const float kp = __shfl_xor_sync(0xffffffffu, kn, 1);
    const float qr = (d & 1) ? qp : -qp;
    const float kr = (d & 1) ? kp : -kp;

    const float cc = rc[(long long)s * HD + d];
    const float sn = rs[(long long)s * HD + d];

    const long long o = ((long long)h * SEQ + s) * HD + d;
    Q[o] = qn * cc + qr * sn;
    K[o] = kn * cc + kr * sn;
    Vt[((long long)h * HD + d) * SEQ + s] = v;
}

// ---------------- row softmax (in place) ----------------
__global__ void softmax_k(float* __restrict__ S, int ncols)
{
    float* r = S + (long long)blockIdx.x * ncols;
    const int tid = threadIdx.x;
    __shared__ float sh[8];

    float m = -INFINITY;
    for (int c = tid; c < ncols; c += 256) m = fmaxf(m, r[c]);
#pragma unroll
    for (int o = 16; o; o >>= 1) m = fmaxf(m, __shfl_xor_sync(0xffffffffu, m, o));
    if ((tid & 31) == 0) sh[tid >> 5] = m;
    __syncthreads();
    float bm = sh[0];
#pragma unroll
    for (int i = 1; i < 8; i++) bm = fmaxf(bm, sh[i]);
    __syncthreads();

    float sum = 0.f;
    for (int c = tid; c < ncols; c += 256) {
        float e = expf(r[c] - bm);
        r[c] = e;
        sum += e;
    }
#pragma unroll
    for (int o = 16; o; o >>= 1) sum += __shfl_xor_sync(0xffffffffu, sum, o);
    if ((tid & 31) == 0) sh[tid >> 5] = sum;
    __syncthreads();
    float bs = 0.f;
#pragma unroll
    for (int i = 0; i < 8; i++) bs += sh[i];
    const float inv = 1.0f / bs;
    for (int c = tid; c < ncols; c += 256) r[c] *= inv;
}

// ---------------- mean of V per dim (rows >= 1536 are uniform softmax) ----------------
__global__ void mean_k(const float* __restrict__ Vt, float* __restrict__ mean)
{
    const int row = blockIdx.x;       // dim index = h*HD + d, 0..3071
    const float* r = Vt + (long long)row * SEQ;
    const int tid = threadIdx.x;
    float s = 0.f;
    for (int c = tid; c < SEQ; c += 256) s += r[c];
#pragma unroll
    for (int o = 16; o; o >>= 1) s += __shfl_xor_sync(0xffffffffu, s, o);
    __shared__ float sh[8];
    if ((tid & 31) == 0) sh[tid >> 5] = s;
    __syncthreads();
    if (tid == 0) {
        float t = 0.f;
#pragma unroll
        for (int i = 0; i < 8; i++) t += sh[i];
        mean[row] = t * (1.0f / SEQ);
    }
}

// vec = mean @ Wo^T + bo  (one warp per output element)
__global__ void gemv_out(const float* __restrict__ mean, const float* __restrict__ Wo,
                         const float* __restrict__ bo, float* __restrict__ vec)
{
    const int j = blockIdx.x * 8 + (threadIdx.x >> 5);
    const int lane = threadIdx.x & 31;
    const float* w = Wo + (long long)j * DIMN;
    float s = 0.f;
    for (int d = lane; d < DIMN; d += 32) s += mean[d] * w[d];
#pragma unroll
    for (int o = 16; o; o >>= 1) s += __shfl_xor_sync(0xffffffffu, s, o);
    if (lane == 0) vec[j] = s + bo[j];
}

// broadcast vec into hid_out rows [1024, 3072)
__global__ void fill_rows(const float* __restrict__ vec, float* __restrict__ out)
{
    const long long i = (long long)blockIdx.x * 256 + threadIdx.x; // float4 index
    const float4 v = ((const float4*)vec)[i % (DIMN / 4)];
    ((float4*)out)[i] = v;
}

// sum split-K partials: Dt[i] = sum_z DtP[z][i]
__global__ void reduce_splitk(const float* __restrict__ P, float* __restrict__ D)
{
    const int i = blockIdx.x * 256 + threadIdx.x;
    float s = 0.f;
#pragma unroll
    for (int z = 0; z < KSPLIT; z++) s += P[(size_t)z * CONDN * RANKN + i];
    D[i] = s;
}

// ---------------- host-side launch helpers ----------------
static void gemm_big(const float* A, const float* B, const float* bias, float* C,
                     int M, int N, int K, int lda, int ldb, int ldc,
                     long long sA, long long sB, long long sC, int batch,
                     float alpha, const float* aptr, float beta)
{
    dim3 gdim((N + 127) / 128, (M + 127) / 128, batch);
    gemm_tf32<BIG_ARGS><<<gdim, 256, BIG_SMEM>>>(A, B, bias, C, M, N, K, lda, ldb, ldc,
                                                 sA, sB, sC, alpha, aptr, beta);
}

static void gemm_small(const float* A, const float* B, const float* bias, float* C,
                       int M, int N, int K, int lda, int ldb, int ldc,
                       long long sA, long long sB, long long sC, int batch,
                       float alpha, const float* aptr, float beta)
{
    dim3 gdim((N + 63) / 64, (M + 63) / 64, batch);
    gemm_tf32<SMALL_ARGS><<<gdim, 128, SMALL_SMEM>>>(A, B, bias, C, M, N, K, lda, ldb, ldc,
                                                     sA, sB, sC, alpha, aptr, beta);
}

extern "C" void kernel_launch(void* const* d_in, const int* in_sizes, int n_in,
                              void* d_out, int out_size)
{
    const float* hidden = (const float*)d_in[0];
    const float* enc    = (const float*)d_in[1];
    const float* rc     = (const float*)d_in[2];
    const float* rs     = (const float*)d_in[3];
    const float* Wq  = (const float*)d_in[4];
    const float* Wk  = (const float*)d_in[5];
    const float* Wv  = (const float*)d_in[6];
    const float* Wqa = (const float*)d_in[7];
    const float* Wka = (const float*)d_in[8];
    const float* Wva = (const float*)d_in[9];
    const float* Wo  = (const float*)d_in[10];
    const float* Woa = (const float*)d_in[11];
    const float* bq  = (const float*)d_in[12];
    const float* bk  = (const float*)d_in[13];
    const float* bv  = (const float*)d_in[14];
    const float* bqa = (const float*)d_in[15];
    const float* bka = (const float*)d_in[16];
    const float* bva = (const float*)d_in[17];
    const float* bo  = (const float*)d_in[18];
    const float* boa = (const float*)d_in[19];
    const float* nqw  = (const float*)d_in[20];
    const float* nkw  = (const float*)d_in[21];
    const float* naqw = (const float*)d_in[22];
    const float* nakw = (const float*)d_in[23];
    const float* qd = (const float*)d_in[24];
    const float* kd = (const float*)d_in[25];
    const float* vd = (const float*)d_in[26];
    const float* qu = (const float*)d_in[27];
    const float* ku = (const float*)d_in[28];
    const float* vu = (const float*)d_in[29];
    const float* lw = (const float*)d_in[30];

    float *Pq, *Pk, *Pv, *Eq, *Ek, *Ev, *Dt, *DtP, *Q, *K, *Vt, *SA, *SB, *AO, *mean, *vec;
    cudaGetSymbolAddress((void**)&Pq, g_Pq);
    cudaGetSymbolAddress((void**)&Pk, g_Pk);
    cudaGetSymbolAddress((void**)&Pv, g_Pv);
    cudaGetSymbolAddress((void**)&Eq, g_Eq);
    cudaGetSymbolAddress((void**)&Ek, g_Ek);
    cudaGetSymbolAddress((void**)&Ev, g_Ev);
    cudaGetSymbolAddress((void**)&Dt, g_Dt);
    cudaGetSymbolAddress((void**)&DtP, g_DtP);
    cudaGetSymbolAddress((void**)&Q,  g_Q);
    cudaGetSymbolAddress((void**)&K,  g_K);
    cudaGetSymbolAddress((void**)&Vt, g_Vt);
    cudaGetSymbolAddress((void**)&SA, g_SA);
    cudaGetSymbolAddress((void**)&SB, g_SB);
    cudaGetSymbolAddress((void**)&AO, g_AO);
    cudaGetSymbolAddress((void**)&mean, g_mean);
    cudaGetSymbolAddress((void**)&vec,  g_vec);

    float* out = (float*)d_out;

    cudaFuncSetAttribute(gemm_tf32<BIG_ARGS>,
                         cudaFuncAttributeMaxDynamicSharedMemorySize, BIG_SMEM);
    cudaFuncSetAttribute(gemm_tf32<SMALL_ARGS>,
                         cudaFuncAttributeMaxDynamicSharedMemorySize, SMALL_SMEM);

    // 1) image-side base projections: P = hidden @ W^T + b   (grid 576, BIG)
    gemm_big(hidden, Wq, bq, Pq, S_HID, DIMN, DIMN, DIMN, DIMN, DIMN, 0, 0, 0, 1, 1.f, nullptr, 0.f);
    gemm_big(hidden, Wk, bk, Pk, S_HID, DIMN, DIMN, DIMN, DIMN, DIMN, 0, 0, 0, 1, 1.f, nullptr, 0.f);
    gemm_big(hidden, Wv, bv, Pv, S_HID, DIMN, DIMN, DIMN, DIMN, DIMN, 0, 0, 0, 1, 1.f, nullptr, 0.f);

    // 2) encoder projections  (M=512 -> SMALL, grid 384)
    gemm_small(enc, Wqa, bqa, Eq, S_ENC, DIMN, DIMN, DIMN, DIMN, DIMN, 0, 0, 0, 1, 1.f, nullptr, 0.f);
    gemm_small(enc, Wka, bka, Ek, S_ENC, DIMN, DIMN, DIMN, DIMN, DIMN, 0, 0, 0, 1, 1.f, nullptr, 0.f);
    gemm_small(enc, Wva, bva, Ev, S_ENC, DIMN, DIMN, DIMN, DIMN, DIMN, 0, 0, 0, 1, 1.f, nullptr, 0.f);

    // 3) LoRA: only hidden rows [2048,3072) survive the mask; sc = lora_w[0]*ALPHA/RANK = lora_w[0]
    //    down-proj: SMALL + split-K=16 (grid 256); up-proj: SMALL (grid 768)
    const float* downs[3] = {qd, kd, vd};
    const float* ups[3]   = {qu, ku, vu};
    float* Ps[3]          = {Pq, Pk, Pv};
    for (int i = 0; i < 3; i++) {
        gemm_small(hidden + (long long)BLOCKL * DIMN, downs[i], nullptr, DtP,
                   CONDN, RANKN, DIMN / KSPLIT, DIMN, DIMN, RANKN,
                   DIMN / KSPLIT, DIMN / KSPLIT, (long long)CONDN * RANKN, KSPLIT,
                   1.f, nullptr, 0.f);
        reduce_splitk<<<(CONDN * RANKN) / 256, 256>>>(DtP, Dt);
        gemm_small(Dt, ups[i], nullptr, Ps[i] + (long long)BLOCKL * DIMN,
                   CONDN, DIMN, RANKN, RANKN, RANKN, DIMN, 0, 0, 0, 1, 1.f, lw, 1.f);
    }

    // 4) heads + RMSNorm + RoPE + concat; V written transposed
    build_qkv<<<dim3(SEQ, HEADS), HD>>>(Pq, Pk, Pv, Eq, Ek, Ev, rc, rs,
                                        nqw, nkw, naqw, nakw, Q, K, Vt);

    // 5) block A: encoder queries (rows 0..511), full keys  (QK big grid 2688)
    gemm_big(Q, K, nullptr, SA, S_ENC, SEQ, HD, HD, HD, SEQ,
             (long long)SEQ * HD, (long long)SEQ * HD, (long long)S_ENC * SEQ, HEADS,
             ATTN_SCALE, nullptr, 0.f);
    softmax_k<<<HEADS * S_ENC, 256>>>(SA, SEQ);
    //    AV: N=HD=128 only -> SMALL (grid 384)
    gemm_small(SA, Vt, nullptr, AO, S_ENC, HD, SEQ, SEQ, SEQ, DIMN,
               (long long)S_ENC * SEQ, (long long)HD * SEQ, HD, HEADS, 1.f, nullptr, 0.f);

    // 6) block B: cond queries (rows 512..1535), keys 512..1535 only
    gemm_big(Q + (long long)S_ENC * HD, K + (long long)S_ENC * HD, nullptr, SB,
             CONDN, CONDN, HD, HD, HD, CONDN,
             (long long)SEQ * HD, (long long)SEQ * HD, (long long)CONDN * CONDN, HEADS,
             ATTN_SCALE, nullptr, 0.f);
    softmax_k<<<HEADS * CONDN, 256>>>(SB, CONDN);
    gemm_small(SB, Vt + S_ENC, nullptr, AO + (long long)S_ENC * DIMN,
               CONDN, HD, CONDN, CONDN, SEQ, DIMN,
               (long long)CONDN * CONDN, (long long)HD * SEQ, HD, HEADS, 1.f, nullptr, 0.f);

    // 7) fully-masked rows -> uniform softmax -> mean of V; out-proj of that row ONCE
    mean_k<<<DIMN, 256>>>(Vt, mean);
    gemv_out<<<DIMN / 8, 256>>>(mean, Wo, bo, vec);

    // 8) output projections
    //    hid_out rows 0..1023 = AO rows 512..1535 @ Wo^T + bo   (BIG grid 192)
    gemm_big(AO + (long long)S_ENC * DIMN, Wo, bo, out,
             CONDN, DIMN, DIMN, DIMN, DIMN, DIMN, 0, 0, 0, 1, 1.f, nullptr, 0.f);
    //    hid_out rows 1024..3071 = broadcast of vec
    fill_rows<<<(NROWS_C * (DIMN / 4)) / 256, 256>>>(vec, out + (long long)CONDN * DIMN);
    //    enc_out = AO rows 0..511 @ Woa^T + boa   (SMALL grid 384)
    gemm_small(AO, Woa, boa, out + (long long)S_HID * DIMN,
               S_ENC, DIMN, DIMN, DIMN, DIMN, DIMN, 0, 0, 0, 1, 1.f, nullptr, 0.f);
}